// round 7
// baseline (speedup 1.0000x reference)
#include <cuda_runtime.h>

#define N_NODES_MAX 100000
#define N_EDGES_MAX 1600000
#define D_FEAT 32
#define SCAN_BLK 1024

// Scratch (no cudaMalloc allowed)
__device__ int    g_deg_out[N_NODES_MAX];
__device__ int    g_deg_in [N_NODES_MAX];
__device__ float  g_norm   [N_NODES_MAX];
__device__ float4 g_x4     [N_NODES_MAX * (D_FEAT / 4)];
__device__ int    g_incl   [N_NODES_MAX];   // per-block inclusive scan
__device__ int    g_bsum   [256];           // block sums (98 used)
__device__ int    g_ofs    [N_NODES_MAX];
__device__ int    g_cur    [N_NODES_MAX];
__device__ int    g_csrc   [N_EDGES_MAX];

// ---------------------------------------------------------------------------
// 1: out-degree of src and in-degree of dst.  int4 main body + thread tail.
// ---------------------------------------------------------------------------
__global__ void k_degrees(const int4* __restrict__ src4,
                          const int4* __restrict__ dst4,
                          const int*  __restrict__ src,
                          const int*  __restrict__ dst,
                          int n4, int n_edges)
{
    int i = blockIdx.x * blockDim.x + threadIdx.x;
    if (i < n4) {
        int4 s = __ldg(&src4[i]);
        int4 d = __ldg(&dst4[i]);
        atomicAdd(&g_deg_out[s.x], 1); atomicAdd(&g_deg_out[s.y], 1);
        atomicAdd(&g_deg_out[s.z], 1); atomicAdd(&g_deg_out[s.w], 1);
        atomicAdd(&g_deg_in [d.x], 1); atomicAdd(&g_deg_in [d.y], 1);
        atomicAdd(&g_deg_in [d.z], 1); atomicAdd(&g_deg_in [d.w], 1);
    } else {
        int e = n4 * 4 + (i - n4);
        if (e < n_edges) {
            atomicAdd(&g_deg_out[src[e]], 1);
            atomicAdd(&g_deg_in [dst[e]], 1);
        }
    }
}

// ---------------------------------------------------------------------------
// 2: norm = rsqrt(out-degree); prescale x = feat * norm.
// ---------------------------------------------------------------------------
__global__ void k_prescale(const float4* __restrict__ feat4, int n_nodes)
{
    int i = blockIdx.x * blockDim.x + threadIdx.x;
    int total4 = n_nodes * (D_FEAT / 4);
    if (i >= total4) return;
    int n = i >> 3;
    int deg = __ldg(&g_deg_out[n]);
    float norm = (deg > 0) ? rsqrtf((float)deg) : 0.0f;
    if ((i & 7) == 0) g_norm[n] = norm;
    float4 f = __ldg(&feat4[i]);
    g_x4[i] = make_float4(f.x * norm, f.y * norm, f.z * norm, f.w * norm);
}

// ---------------------------------------------------------------------------
// 3: per-block inclusive scan of in-degrees (shuffle-based) + block sums.
// ---------------------------------------------------------------------------
__global__ void k_scanA(int n_nodes)
{
    __shared__ int wsum[32];
    int tid  = threadIdx.x;
    int lane = tid & 31;
    int wid  = tid >> 5;
    int gid  = blockIdx.x * SCAN_BLK + tid;

    int v = (gid < n_nodes) ? g_deg_in[gid] : 0;
    int x = v;
    #pragma unroll
    for (int off = 1; off < 32; off <<= 1) {
        int y = __shfl_up_sync(0xffffffff, x, off);
        if (lane >= off) x += y;
    }
    if (lane == 31) wsum[wid] = x;
    __syncthreads();
    if (wid == 0) {
        int w = wsum[lane];
        #pragma unroll
        for (int off = 1; off < 32; off <<= 1) {
            int y = __shfl_up_sync(0xffffffff, w, off);
            if (lane >= off) w += y;
        }
        wsum[lane] = w;
    }
    __syncthreads();
    int incl = x + ((wid > 0) ? wsum[wid - 1] : 0);
    if (gid < n_nodes) g_incl[gid] = incl;
    if (tid == SCAN_BLK - 1) g_bsum[blockIdx.x] = incl;
}

// ---------------------------------------------------------------------------
// 4: fused block-sum scan + apply.  Every block redundantly scans the
// (<=128) block sums in smem, then writes ofs/cur for its nodes.
// ---------------------------------------------------------------------------
__global__ void k_scanBC(int n_nodes, int nblocks)
{
    __shared__ int bs[2][128];
    int tid = threadIdx.x;
    if (tid < 128) bs[0][tid] = (tid < nblocks) ? g_bsum[tid] : 0;
    __syncthreads();
    int buf = 0;
    #pragma unroll
    for (int off = 1; off < 128; off <<= 1) {
        if (tid < 128)
            bs[buf ^ 1][tid] = bs[buf][tid] + ((tid >= off) ? bs[buf][tid - off] : 0);
        buf ^= 1;
        __syncthreads();
    }
    int gid = blockIdx.x * SCAN_BLK + tid;
    if (gid >= n_nodes) return;
    int bpre = (blockIdx.x > 0) ? bs[buf][blockIdx.x - 1] : 0;
    int ofs = bpre + g_incl[gid] - g_deg_in[gid];
    g_ofs[gid] = ofs;
    g_cur[gid] = ofs;
}

// ---------------------------------------------------------------------------
// 5: bucket edges by dst: csrc[pos] = src.
// ---------------------------------------------------------------------------
__global__ void k_bucket(const int4* __restrict__ src4,
                         const int4* __restrict__ dst4,
                         const int*  __restrict__ src,
                         const int*  __restrict__ dst,
                         int n4, int n_edges)
{
    int i = blockIdx.x * blockDim.x + threadIdx.x;
    if (i < n4) {
        int4 s = __ldg(&src4[i]);
        int4 d = __ldg(&dst4[i]);
        int p0 = atomicAdd(&g_cur[d.x], 1);
        int p1 = atomicAdd(&g_cur[d.y], 1);
        int p2 = atomicAdd(&g_cur[d.z], 1);
        int p3 = atomicAdd(&g_cur[d.w], 1);
        g_csrc[p0] = s.x; g_csrc[p1] = s.y;
        g_csrc[p2] = s.z; g_csrc[p3] = s.w;
    } else {
        int e = n4 * 4 + (i - n4);
        if (e < n_edges) {
            int p = atomicAdd(&g_cur[dst[e]], 1);
            g_csrc[p] = src[e];
        }
    }
}

// ---------------------------------------------------------------------------
// 6: gather.  One warp per node: 4 edge-groups x 8 feature-lanes, all
// working the same node (no intra-warp length divergence).  Per in-edge one
// LDG.128 of prescaled x[src]; fp32 register accumulation; cross-group
// shuffle reduce; one streaming write of out[t] = acc * norm[t].
// ---------------------------------------------------------------------------
__global__ void k_gather(float4* __restrict__ out4, int n_nodes)
{
    int gtid = blockIdx.x * blockDim.x + threadIdx.x;
    int t    = gtid >> 5;                  // node = warp
    int lane = gtid & 31;
    int grp  = lane >> 3;                  // 0..3 edge group
    int c    = lane & 7;                   // float4 chunk
    if (t >= n_nodes) return;

    int start = __ldg(&g_ofs[t]);
    int len   = __ldg(&g_deg_in[t]);

    float4 a0 = make_float4(0.f, 0.f, 0.f, 0.f);
    float4 a1 = make_float4(0.f, 0.f, 0.f, 0.f);

    int j = grp;
    for (; j + 4 < len; j += 8) {
        int s0 = __ldg(&g_csrc[start + j]);
        int s1 = __ldg(&g_csrc[start + j + 4]);
        float4 f0 = __ldg(&g_x4[s0 * (D_FEAT / 4) + c]);
        float4 f1 = __ldg(&g_x4[s1 * (D_FEAT / 4) + c]);
        a0.x += f0.x; a0.y += f0.y; a0.z += f0.z; a0.w += f0.w;
        a1.x += f1.x; a1.y += f1.y; a1.z += f1.z; a1.w += f1.w;
    }
    if (j < len) {
        int s0 = __ldg(&g_csrc[start + j]);
        float4 f0 = __ldg(&g_x4[s0 * (D_FEAT / 4) + c]);
        a0.x += f0.x; a0.y += f0.y; a0.z += f0.z; a0.w += f0.w;
    }
    a0.x += a1.x; a0.y += a1.y; a0.z += a1.z; a0.w += a1.w;

    // reduce across the 4 edge groups (lanes differing in bits 3,4)
    #pragma unroll
    for (int off = 8; off <= 16; off <<= 1) {
        a0.x += __shfl_xor_sync(0xffffffff, a0.x, off);
        a0.y += __shfl_xor_sync(0xffffffff, a0.y, off);
        a0.z += __shfl_xor_sync(0xffffffff, a0.z, off);
        a0.w += __shfl_xor_sync(0xffffffff, a0.w, off);
    }

    if (grp == 0) {
        float nrm = __ldg(&g_norm[t]);
        out4[t * (D_FEAT / 4) + c] =
            make_float4(a0.x * nrm, a0.y * nrm, a0.z * nrm, a0.w * nrm);
    }
}

extern "C" void kernel_launch(void* const* d_in, const int* in_sizes, int n_in,
                              void* d_out, int out_size)
{
    const float* features = (const float*)d_in[0];
    const int*   src      = (const int*)d_in[1];
    const int*   dst      = (const int*)d_in[2];
    float*       out      = (float*)d_out;

    int n_nodes = in_sizes[0] / D_FEAT;   // 100000
    int n_edges = in_sizes[1];            // 1600000

    const int TPB = 256;
    int total4 = n_nodes * (D_FEAT / 4);
    int n4  = n_edges / 4;
    int rem = n_edges - n4 * 4;
    int scan_blocks = (n_nodes + SCAN_BLK - 1) / SCAN_BLK;   // 98

    // zero both degree arrays with one async memset each (graph-capturable)
    void* p_dout; cudaGetSymbolAddress(&p_dout, g_deg_out);
    void* p_din;  cudaGetSymbolAddress(&p_din,  g_deg_in);
    cudaMemsetAsync(p_dout, 0, n_nodes * sizeof(int));
    cudaMemsetAsync(p_din,  0, n_nodes * sizeof(int));

    int work = n4 + rem;
    k_degrees<<<(work + TPB - 1) / TPB, TPB>>>((const int4*)src, (const int4*)dst,
                                               src, dst, n4, n_edges);

    k_prescale<<<(total4 + TPB - 1) / TPB, TPB>>>((const float4*)features, n_nodes);

    k_scanA<<<scan_blocks, SCAN_BLK>>>(n_nodes);
    k_scanBC<<<scan_blocks, SCAN_BLK>>>(n_nodes, scan_blocks);

    k_bucket<<<(work + TPB - 1) / TPB, TPB>>>((const int4*)src, (const int4*)dst,
                                              src, dst, n4, n_edges);

    long long threads = (long long)n_nodes * 32;
    int blocks = (int)((threads + TPB - 1) / TPB);
    k_gather<<<blocks, TPB>>>((float4*)out, n_nodes);
}